// round 3
// baseline (speedup 1.0000x reference)
#include <cuda_runtime.h>
#include <cuda_bf16.h>

#define NN 32768
#define KC 16
#define AST 260  // A smem row stride in floats (256 + 4 pad)

// ---------------- device-global scratch (no allocations allowed) ----------------
__device__ float g_B1[256 * 768];      // combined K1 B matrix [k][col]
__device__ float g_bias1[768];
__device__ float g_sw[2u * NN * 512];  // softmax slice weights (b,n,h*64+g)  128MB
__device__ float g_fx[2u * NN * 256];  // fx projection (b,n,h*32+c)          64MB
__device__ float g_num[2 * 8 * 64 * 32];
__device__ float g_den[2 * 8 * 64];
__device__ float g_M[2 * 512 * 256];   // folded att@Wout

__device__ __forceinline__ void ffma2(unsigned long long& c, unsigned long long a,
                                      unsigned long long b) {
    asm("fma.rn.f32x2 %0, %1, %2, %0;" : "+l"(c) : "l"(a), "l"(b));
}
__device__ __forceinline__ float f2lo(unsigned long long u) { return __uint_as_float((unsigned)u); }
__device__ __forceinline__ float f2hi(unsigned long long u) { return __uint_as_float((unsigned)(u >> 32)); }

// ---------------- shared 128x128 f32x2 GEMM core (256 threads, 8x8/thread) ------
__device__ __forceinline__ void gemm128(const float* __restrict__ A, int lda, int ktot,
                                        const float* __restrict__ Bm, int bld, int colbase,
                                        float* Ast, float* Bs,
                                        unsigned long long (&acc)[8][4]) {
    const int tid = threadIdx.x;
    const int tx = tid & 15, ty = tid >> 4;
    for (int kc = 0; kc < ktot; kc += KC) {
        __syncthreads();
        {   // stage A (128 rows x KC k), duplicated pairs: Ast[k][2r]=Ast[k][2r+1]=A[r][k]
            int kk = tid & 15, rr = tid >> 4;
            #pragma unroll
            for (int r = 0; r < 128; r += 16) {
                float v = A[(r + rr) * lda + kc + kk];
                *(float2*)&Ast[kk * AST + 2 * (r + rr)] = make_float2(v, v);
            }
        }
        {   // stage B (KC k x 128 cols)
            int c4 = (tid & 31) * 4, k0 = tid >> 5;
            #pragma unroll
            for (int k = 0; k < KC; k += 8)
                *(float4*)&Bs[(k + k0) * 128 + c4] =
                    *(const float4*)&Bm[(kc + k + k0) * bld + colbase + c4];
        }
        __syncthreads();
        #pragma unroll 4
        for (int k = 0; k < KC; ++k) {
            ulonglong2 au[4];
            unsigned long long bu[4];
            #pragma unroll
            for (int s = 0; s < 4; ++s)
                au[s] = *(const ulonglong2*)&Ast[k * AST + 4 * ty + 64 * s];
            #pragma unroll
            for (int j = 0; j < 4; ++j)
                bu[j] = *(const unsigned long long*)&Bs[k * 128 + tx * 2 + 32 * j];
            #pragma unroll
            for (int s = 0; s < 4; ++s)
                #pragma unroll
                for (int j = 0; j < 4; ++j) {
                    ffma2(acc[2 * s + 0][j], au[s].x, bu[j]);
                    ffma2(acc[2 * s + 1][j], au[s].y, bu[j]);
                }
        }
    }
}

// ---------------- K0: build folded B1 + bias ----------------
__global__ void k0(const float* __restrict__ Wx, const float* __restrict__ bx,
                   const float* __restrict__ Wfx, const float* __restrict__ bfx,
                   const float* __restrict__ Wsl, const float* __restrict__ bsl,
                   const float* __restrict__ temp) {
    int col = blockIdx.x, d = threadIdx.x;
    if (col < 512) {
        int h = col >> 6, g = col & 63;
        float s = 0.f;
        #pragma unroll
        for (int c = 0; c < 32; ++c) s += Wx[(h * 32 + c) * 256 + d] * Wsl[g * 32 + c];
        float it = 1.0f / temp[h];
        g_B1[d * 768 + col] = s * it;
        if (d == 0) {
            float sb = bsl[g];
            for (int c = 0; c < 32; ++c) sb += bx[h * 32 + c] * Wsl[g * 32 + c];
            g_bias1[col] = sb * it;
        }
    } else {
        int o = col - 512;
        g_B1[d * 768 + col] = Wfx[o * 256 + d];
        if (d == 0) g_bias1[col] = bfx[o];
    }
}

__global__ void kzero() {
    int i = blockIdx.x * 256 + threadIdx.x;
    if (i < 2 * 8 * 64 * 32) g_num[i] = 0.f;
    int j = i - 2 * 8 * 64 * 32;
    if (j >= 0 && j < 2 * 8 * 64) g_den[j] = 0.f;
}

// ---------------- K1: S = x@B1 + bias; softmax(64-groups) -> g_sw; raw -> g_fx ---
__global__ __launch_bounds__(256) void k1(const float* __restrict__ x) {
    __shared__ float Ast[KC * AST];
    __shared__ float Bs[KC * 128];
    const int b = blockIdx.x >> 8;
    const int t0 = (blockIdx.x & 255) * 128;
    const int ct = blockIdx.y;  // 0..5

    unsigned long long acc[8][4];
    #pragma unroll
    for (int i = 0; i < 8; ++i)
        #pragma unroll
        for (int j = 0; j < 4; ++j) acc[i][j] = 0ULL;

    gemm128(x + (b * NN + t0) * 256, 256, 256, g_B1, 768, ct * 128, Ast, Bs, acc);

    const int tid = threadIdx.x, tx = tid & 15, ty = tid >> 4;
    float bb[4][2];
    #pragma unroll
    for (int j = 0; j < 4; ++j) {
        bb[j][0] = g_bias1[ct * 128 + tx * 2 + 32 * j];
        bb[j][1] = g_bias1[ct * 128 + tx * 2 + 32 * j + 1];
    }
    #pragma unroll
    for (int s = 0; s < 4; ++s)
        #pragma unroll
        for (int e = 0; e < 2; ++e) {
            int row = t0 + 2 * ty + 32 * s + e;
            float v[4][2];
            #pragma unroll
            for (int j = 0; j < 4; ++j) {
                v[j][0] = f2lo(acc[2 * s + e][j]) + bb[j][0];
                v[j][1] = f2hi(acc[2 * s + e][j]) + bb[j][1];
            }
            if (ct < 4) {
                int base = (b * NN + row) * 512 + ct * 128;
                #pragma unroll
                for (int grp = 0; grp < 2; ++grp) {
                    int j0 = 2 * grp;
                    float m = fmaxf(fmaxf(v[j0][0], v[j0][1]), fmaxf(v[j0 + 1][0], v[j0 + 1][1]));
                    #pragma unroll
                    for (int o = 1; o < 16; o <<= 1) m = fmaxf(m, __shfl_xor_sync(0xffffffffu, m, o));
                    float e00 = __expf(v[j0][0] - m), e01 = __expf(v[j0][1] - m);
                    float e10 = __expf(v[j0 + 1][0] - m), e11 = __expf(v[j0 + 1][1] - m);
                    float ss = e00 + e01 + e10 + e11;
                    #pragma unroll
                    for (int o = 1; o < 16; o <<= 1) ss += __shfl_xor_sync(0xffffffffu, ss, o);
                    float inv = 1.0f / ss;
                    g_sw[base + tx * 2 + 32 * j0] = e00 * inv;
                    g_sw[base + tx * 2 + 32 * j0 + 1] = e01 * inv;
                    g_sw[base + tx * 2 + 32 * (j0 + 1)] = e10 * inv;
                    g_sw[base + tx * 2 + 32 * (j0 + 1) + 1] = e11 * inv;
                }
            } else {
                int fb = (b * NN + row) * 256 + (ct - 4) * 128;
                #pragma unroll
                for (int j = 0; j < 4; ++j) {
                    g_fx[fb + tx * 2 + 32 * j] = v[j][0];
                    g_fx[fb + tx * 2 + 32 * j + 1] = v[j][1];
                }
            }
        }
}

// ---------------- K2: num = sw^T @ fx, den = colsum(sw), split over N + atomics --
__global__ __launch_bounds__(256) void k2() {
    __shared__ float sws[32][64];
    __shared__ float fxs[32][32];
    const int bh = blockIdx.y, b = bh >> 3, h = bh & 7;
    const int n0 = blockIdx.x * 1024;
    const int tid = threadIdx.x;
    const int g = tid >> 2, cq = tid & 3;
    float acc[8] = {0, 0, 0, 0, 0, 0, 0, 0};
    float dacc = 0.f;
    for (int nt = 0; nt < 1024; nt += 32) {
        __syncthreads();
        int rr = tid >> 3, p = tid & 7;
        int n = n0 + nt + rr;
        *(float4*)&sws[rr][p * 8] = *(const float4*)&g_sw[(b * NN + n) * 512 + h * 64 + p * 8];
        *(float4*)&sws[rr][p * 8 + 4] = *(const float4*)&g_sw[(b * NN + n) * 512 + h * 64 + p * 8 + 4];
        if (p < 8) {  // 32x32 fx tile: 8 float4 slots per row
            // (every thread participates: p indexes 8 float4 columns of 32 floats? 32 floats = 8 float4)
        }
        *(float4*)&fxs[rr][(tid & 7) * 4] = *(const float4*)&g_fx[(b * NN + n) * 256 + h * 32 + (tid & 7) * 4];
        __syncthreads();
        #pragma unroll 8
        for (int nn = 0; nn < 32; ++nn) {
            float s = sws[nn][g];
            if (cq == 0) dacc += s;
            float4 fa = *(float4*)&fxs[nn][cq * 8];
            float4 fb = *(float4*)&fxs[nn][cq * 8 + 4];
            acc[0] += s * fa.x; acc[1] += s * fa.y; acc[2] += s * fa.z; acc[3] += s * fa.w;
            acc[4] += s * fb.x; acc[5] += s * fb.y; acc[6] += s * fb.z; acc[7] += s * fb.w;
        }
    }
    int ob = (bh * 64 + g) * 32 + cq * 8;
    #pragma unroll
    for (int i = 0; i < 8; ++i) atomicAdd(&g_num[ob + i], acc[i]);
    if (cq == 0) atomicAdd(&g_den[bh * 64 + g], dacc);
}

// ---------------- K3: slice_att -> qkv -> 64x64 SDPA -> fold Wout into M --------
__global__ __launch_bounds__(256) void k3(const float* __restrict__ Wqkv,
                                          const float* __restrict__ Wout) {
    __shared__ float sa[64 * 32];  // slice_att, later att
    __shared__ float qs[64 * 32], ks2[64 * 32], vs[64 * 32];
    __shared__ float wq[96 * 32];
    const int bh = blockIdx.x, b = bh >> 3, h = bh & 7;
    const int tid = threadIdx.x;
    for (int i = tid; i < 96 * 32; i += 256) wq[i] = Wqkv[i];
    #pragma unroll
    for (int c = 0; c < 8; ++c) {
        int idx = tid * 8 + c;
        int g = idx >> 5;
        sa[idx] = g_num[bh * 2048 + idx] / (g_den[bh * 64 + g] + 1e-5f);
    }
    __syncthreads();
    for (int t = tid; t < 6144; t += 256) {
        int g = t & 63, j = t >> 6;
        float s2 = 0.f;
        #pragma unroll
        for (int c = 0; c < 32; ++c) s2 += sa[g * 32 + c] * wq[j * 32 + c];
        if (j < 32) qs[g * 32 + j] = s2;
        else if (j < 64) ks2[g * 32 + (j - 32)] = s2;
        else vs[g * 32 + (j - 64)] = s2;
    }
    __syncthreads();
    if (tid < 64) {
        int g = tid;
        float sc[64], m = -1e30f;
        #pragma unroll 8
        for (int kk = 0; kk < 64; ++kk) {
            float s2 = 0.f;
            #pragma unroll
            for (int c = 0; c < 32; ++c) s2 += qs[g * 32 + c] * ks2[kk * 32 + c];
            s2 *= 0.17677669529663687f;  // 32^-0.5
            sc[kk] = s2;
            m = fmaxf(m, s2);
        }
        float ssum = 0.f;
        #pragma unroll
        for (int kk = 0; kk < 64; ++kk) { sc[kk] = __expf(sc[kk] - m); ssum += sc[kk]; }
        float inv = 1.0f / ssum;
        float att[32];
        #pragma unroll
        for (int c = 0; c < 32; ++c) att[c] = 0.f;
        #pragma unroll 8
        for (int kk = 0; kk < 64; ++kk) {
            float p = sc[kk] * inv;
            #pragma unroll
            for (int c = 0; c < 32; ++c) att[c] += p * vs[kk * 32 + c];
        }
        __syncwarp();
        #pragma unroll
        for (int c = 0; c < 32; ++c) sa[g * 32 + c] = att[c];
    }
    __syncthreads();
    // M[hg][d2] = sum_c att[g][c]*Wout[d2][h*32+c]
    for (int g = 0; g < 64; ++g) {
        int d2 = tid;
        float s2 = 0.f;
        #pragma unroll
        for (int c = 0; c < 32; ++c) s2 += sa[g * 32 + c] * Wout[d2 * 256 + h * 32 + c];
        g_M[b * 512 * 256 + (h * 64 + g) * 256 + d2] = s2;
    }
}

// ---------------- K4: out = sw @ M + bout ----------------
__global__ __launch_bounds__(256) void k4(float* __restrict__ out,
                                          const float* __restrict__ bout) {
    __shared__ float Ast[KC * AST];
    __shared__ float Bs[KC * 128];
    const int b = blockIdx.x >> 8;
    const int t0 = (blockIdx.x & 255) * 128;
    const int ct = blockIdx.y;  // 0..1

    unsigned long long acc[8][4];
    #pragma unroll
    for (int i = 0; i < 8; ++i)
        #pragma unroll
        for (int j = 0; j < 4; ++j) acc[i][j] = 0ULL;

    gemm128(g_sw + (unsigned)(b * NN + t0) * 512, 512, 512,
            g_M + b * 512 * 256, 256, ct * 128, Ast, Bs, acc);

    const int tid = threadIdx.x, tx = tid & 15, ty = tid >> 4;
    #pragma unroll
    for (int s = 0; s < 4; ++s)
        #pragma unroll
        for (int e = 0; e < 2; ++e) {
            int row = t0 + 2 * ty + 32 * s + e;
            float* op = out + (unsigned)(b * NN + row) * 256 + ct * 128;
            #pragma unroll
            for (int j = 0; j < 4; ++j) {
                int col = tx * 2 + 32 * j;
                op[col] = f2lo(acc[2 * s + e][j]) + bout[ct * 128 + col];
                op[col + 1] = f2hi(acc[2 * s + e][j]) + bout[ct * 128 + col + 1];
            }
        }
}

extern "C" void kernel_launch(void* const* d_in, const int* in_sizes, int n_in,
                              void* d_out, int out_size) {
    const float* x = (const float*)d_in[0];
    const float* Wx = (const float*)d_in[1];
    const float* bx = (const float*)d_in[2];
    const float* Wfx = (const float*)d_in[3];
    const float* bfx = (const float*)d_in[4];
    const float* Wsl = (const float*)d_in[5];
    const float* bsl = (const float*)d_in[6];
    const float* temp = (const float*)d_in[7];
    const float* Wqkv = (const float*)d_in[8];
    const float* Wout = (const float*)d_in[9];
    const float* bout = (const float*)d_in[10];
    float* out = (float*)d_out;

    k0<<<768, 256>>>(Wx, bx, Wfx, bfx, Wsl, bsl, temp);
    kzero<<<(2 * 8 * 64 * 32 + 2 * 8 * 64 + 255) / 256, 256>>>();
    k1<<<dim3(512, 6), 256>>>(x);
    k2<<<dim3(32, 16), 256>>>();
    k3<<<16, 256>>>(Wqkv, Wout);
    k4<<<dim3(512, 2), 256>>>(out, bout);
}

// round 5
// speedup vs baseline: 2.1201x; 2.1201x over previous
#include <cuda_runtime.h>
#include <cuda_bf16.h>
#include <cstdint>

#define NN 32768
#define SWZ(o) ((o) ^ (((o) >> 3) & 0x70))

__device__ __align__(128) __nv_bfloat16 g_xh[(size_t)2 * NN * 256];
__device__ __align__(128) __nv_bfloat16 g_xl[(size_t)2 * NN * 256];
__device__ __align__(128) __nv_bfloat16 g_B1b[768u * 768];
__device__ __align__(128) float g_bias1[768];
__device__ __align__(128) __nv_bfloat16 g_swh[(size_t)2 * NN * 512];
__device__ __align__(128) __nv_bfloat16 g_swl[(size_t)2 * NN * 512];
__device__ __align__(128) float g_fx[(size_t)2 * NN * 256];
__device__ __align__(128) float g_num[2 * 8 * 64 * 32];
__device__ __align__(128) float g_den[2 * 8 * 64];
__device__ __align__(128) __nv_bfloat16 g_Mb[(size_t)2 * 256 * 1536];

__device__ __forceinline__ uint32_t s2u(const void* p) {
    uint32_t a;
    asm("{ .reg .u64 t; cvta.to.shared.u64 t, %1; cvt.u32.u64 %0, t; }" : "=r"(a) : "l"(p));
    return a;
}
__device__ __forceinline__ void cpa16(uint32_t dst, const void* src) {
    asm volatile("cp.async.cg.shared.global [%0], [%1], 16;" :: "r"(dst), "l"(src));
}
__device__ __forceinline__ void cpa_commit() { asm volatile("cp.async.commit_group;" ::: "memory"); }
template <int N>
__device__ __forceinline__ void cpa_wait() { asm volatile("cp.async.wait_group %0;" :: "n"(N) : "memory"); }

// stage a 128x64 bf16 tile (rows x k) into swizzled 128B-row smem
__device__ __forceinline__ void stage(uint32_t sbase, const __nv_bfloat16* __restrict__ src, int ld) {
    int t = threadIdx.x;
    #pragma unroll
    for (int i = 0; i < 4; ++i) {
        int idx = t + i * 256;
        int row = idx >> 3, ch = idx & 7;
        cpa16(sbase + SWZ(row * 128 + ch * 16), src + (size_t)row * ld + ch * 8);
    }
}

__device__ __forceinline__ void ldsm4(uint32_t* r, uint32_t addr) {
    asm volatile("ldmatrix.sync.aligned.m8n8.x4.shared.b16 {%0,%1,%2,%3}, [%4];"
                 : "=r"(r[0]), "=r"(r[1]), "=r"(r[2]), "=r"(r[3]) : "r"(addr));
}
__device__ __forceinline__ void mma_bf16(float* c, const uint32_t* a, uint32_t b0, uint32_t b1) {
    asm volatile("mma.sync.aligned.m16n8k16.row.col.f32.bf16.bf16.f32 "
                 "{%0,%1,%2,%3},{%4,%5,%6,%7},{%8,%9},{%0,%1,%2,%3};"
                 : "+f"(c[0]), "+f"(c[1]), "+f"(c[2]), "+f"(c[3])
                 : "r"(a[0]), "r"(a[1]), "r"(a[2]), "r"(a[3]), "r"(b0), "r"(b1));
}

// one 64-k chunk: warp (wm 0..3, wn 0..1) computes 32x64 of the 128x128 tile
__device__ __forceinline__ void compute_chunk(uint32_t abase, uint32_t bbase, int wm, int wn,
                                              int lane, float (&acc)[2][8][4]) {
    const int l15 = lane & 15, l16 = (lane >> 4) << 4;
    uint32_t arb[2], brb[4];
    int asz[2], bsz[4];
    #pragma unroll
    for (int mf = 0; mf < 2; ++mf) {
        int r = wm * 32 + mf * 16 + l15;
        arb[mf] = abase + r * 128;
        asz[mf] = (r & 7) << 4;
    }
    #pragma unroll
    for (int ng = 0; ng < 4; ++ng) {
        int r = wn * 64 + ng * 16 + l15;
        brb[ng] = bbase + r * 128;
        bsz[ng] = (r & 7) << 4;
    }
    #pragma unroll
    for (int ks = 0; ks < 4; ++ks) {
        uint32_t a[2][4], bq[4][4];
        int cb = ks * 32 + l16;
        #pragma unroll
        for (int mf = 0; mf < 2; ++mf) ldsm4(a[mf], arb[mf] + (cb ^ asz[mf]));
        #pragma unroll
        for (int ng = 0; ng < 4; ++ng) ldsm4(bq[ng], brb[ng] + (cb ^ bsz[ng]));
        #pragma unroll
        for (int mf = 0; mf < 2; ++mf)
            #pragma unroll
            for (int nf = 0; nf < 8; ++nf)
                mma_bf16(acc[mf][nf], a[mf], bq[nf >> 1][nf & 1], bq[nf >> 1][2 + (nf & 1)]);
    }
}

// ---------------- K0: folded B1 (bf16 hi/lo/hi) + bias ----------------
__global__ void k0(const float* __restrict__ Wx, const float* __restrict__ bx,
                   const float* __restrict__ Wfx, const float* __restrict__ bfx,
                   const float* __restrict__ Wsl, const float* __restrict__ bsl,
                   const float* __restrict__ temp) {
    int col = blockIdx.x, d = threadIdx.x;
    float v;
    if (col < 512) {
        int h = col >> 6, g = col & 63;
        float s = 0.f;
        #pragma unroll
        for (int c = 0; c < 32; ++c) s += Wx[(h * 32 + c) * 256 + d] * Wsl[g * 32 + c];
        float it = 1.0f / temp[h];
        v = s * it;
        if (d == 0) {
            float sb = bsl[g];
            for (int c = 0; c < 32; ++c) sb += bx[h * 32 + c] * Wsl[g * 32 + c];
            g_bias1[col] = sb * it;
        }
    } else {
        v = Wfx[(col - 512) * 256 + d];
        if (d == 0) g_bias1[col] = bfx[col - 512];
    }
    __nv_bfloat16 h16 = __float2bfloat16(v);
    __nv_bfloat16 l16 = __float2bfloat16(v - __bfloat162float(h16));
    g_B1b[(size_t)col * 768 + d] = h16;
    g_B1b[(size_t)col * 768 + 256 + d] = l16;
    g_B1b[(size_t)col * 768 + 512 + d] = h16;
}

__global__ void kprep(const float* __restrict__ x) {
    size_t i = ((size_t)blockIdx.x * 256 + threadIdx.x) * 4;
    float4 v = *(const float4*)(x + i);
    __nv_bfloat162 ha, hb, la, lb;
    ha.x = __float2bfloat16(v.x); ha.y = __float2bfloat16(v.y);
    hb.x = __float2bfloat16(v.z); hb.y = __float2bfloat16(v.w);
    la.x = __float2bfloat16(v.x - __bfloat162float(ha.x));
    la.y = __float2bfloat16(v.y - __bfloat162float(ha.y));
    lb.x = __float2bfloat16(v.z - __bfloat162float(hb.x));
    lb.y = __float2bfloat16(v.w - __bfloat162float(hb.y));
    *(uint2*)&g_xh[i] = make_uint2(*(uint32_t*)&ha, *(uint32_t*)&hb);
    *(uint2*)&g_xl[i] = make_uint2(*(uint32_t*)&la, *(uint32_t*)&lb);
}

__global__ void kzero() {
    int i = blockIdx.x * 256 + threadIdx.x;
    if (i < 2 * 8 * 64 * 32) g_num[i] = 0.f;
    int j = i - 2 * 8 * 64 * 32;
    if (j >= 0 && j < 2 * 8 * 64) g_den[j] = 0.f;
}

// ---------------- K1: [128x128] mma.sync GEMM over K'=768, fused softmax / fx ----
__global__ __launch_bounds__(256) void k1() {
    extern __shared__ char sm[];
    uint32_t sb = s2u(sm);
    const int tid = threadIdx.x, lane = tid & 31, wid = tid >> 5;
    const int wm = wid & 3, wn = wid >> 2;
    const int y = blockIdx.x;                    // 0..5 column tile (y-major for L2 reuse)
    const int b = blockIdx.y >> 8, t0 = (blockIdx.y & 255) * 128;
    float* bias = (float*)(sm + 65536);
    if (tid < 128) bias[tid] = g_bias1[y * 128 + tid];

    const __nv_bfloat16* xh = g_xh + (size_t)(b * NN + t0) * 256;
    const __nv_bfloat16* xl = g_xl + (size_t)(b * NN + t0) * 256;
    const __nv_bfloat16* Bsrc = g_B1b + (size_t)(y * 128) * 768;

    float acc[2][8][4];
    #pragma unroll
    for (int i = 0; i < 2; ++i)
        #pragma unroll
        for (int j = 0; j < 8; ++j)
            #pragma unroll
            for (int k = 0; k < 4; ++k) acc[i][j][k] = 0.f;

    const int NCHK = 12;
    stage(sb, xh, 256);
    stage(sb + 32768, Bsrc, 768);
    cpa_commit();
    #pragma unroll 1
    for (int c = 0; c < NCHK; ++c) {
        uint32_t ab = sb + (c & 1) * 16384, bb = sb + 32768 + (c & 1) * 16384;
        if (c + 1 < NCHK) {
            int kc = (c + 1) * 64;
            const __nv_bfloat16* as = (kc < 512) ? xh + (kc & 255) : xl + (kc - 512);
            stage(sb + ((c + 1) & 1) * 16384, as, 256);
            stage(sb + 32768 + ((c + 1) & 1) * 16384, Bsrc + kc, 768);
            cpa_commit();
            cpa_wait<1>();
        } else {
            cpa_wait<0>();
        }
        __syncthreads();
        compute_chunk(ab, bb, wm, wn, lane, acc);
        __syncthreads();
    }

    const int q = lane & 3, qr = lane >> 2;
    const int cbl = wn * 64;
    #pragma unroll
    for (int mf = 0; mf < 2; ++mf)
        #pragma unroll
        for (int half = 0; half < 2; ++half) {
            int rl = wm * 32 + mf * 16 + qr + half * 8;
            size_t rb = (size_t)(b * NN + t0 + rl);
            float v[8][2];
            #pragma unroll
            for (int nf = 0; nf < 8; ++nf) {
                v[nf][0] = acc[mf][nf][half * 2 + 0] + bias[cbl + nf * 8 + q * 2 + 0];
                v[nf][1] = acc[mf][nf][half * 2 + 1] + bias[cbl + nf * 8 + q * 2 + 1];
            }
            if (y < 4) {
                float m = v[0][0];
                #pragma unroll
                for (int nf = 0; nf < 8; ++nf) m = fmaxf(m, fmaxf(v[nf][0], v[nf][1]));
                m = fmaxf(m, __shfl_xor_sync(0xffffffffu, m, 1));
                m = fmaxf(m, __shfl_xor_sync(0xffffffffu, m, 2));
                float s = 0.f;
                #pragma unroll
                for (int nf = 0; nf < 8; ++nf) {
                    v[nf][0] = __expf(v[nf][0] - m);
                    v[nf][1] = __expf(v[nf][1] - m);
                    s += v[nf][0] + v[nf][1];
                }
                s += __shfl_xor_sync(0xffffffffu, s, 1);
                s += __shfl_xor_sync(0xffffffffu, s, 2);
                float inv = 1.0f / s;
                size_t base = rb * 512 + y * 128 + cbl;
                #pragma unroll
                for (int nf = 0; nf < 8; ++nf) {
                    float a = v[nf][0] * inv, bq2 = v[nf][1] * inv;
                    __nv_bfloat162 hp, lp;
                    hp.x = __float2bfloat16(a); hp.y = __float2bfloat16(bq2);
                    lp.x = __float2bfloat16(a - __bfloat162float(hp.x));
                    lp.y = __float2bfloat16(bq2 - __bfloat162float(hp.y));
                    *(uint32_t*)&g_swh[base + nf * 8 + q * 2] = *(uint32_t*)&hp;
                    *(uint32_t*)&g_swl[base + nf * 8 + q * 2] = *(uint32_t*)&lp;
                }
            } else {
                size_t base = rb * 256 + (y - 4) * 128 + cbl;
                #pragma unroll
                for (int nf = 0; nf < 8; ++nf)
                    *(float2*)&g_fx[base + nf * 8 + q * 2] = make_float2(v[nf][0], v[nf][1]);
            }
        }
}

// ---------------- K2: num = sw^T @ fx, den = colsum(sw) ----------------
__global__ __launch_bounds__(256) void k2() {
    __shared__ float sws[32][68];
    __shared__ float fxs[32][36];
    const int bh = blockIdx.y, b = bh >> 3, h = bh & 7;
    const int n0 = blockIdx.x * 1024;
    const int tid = threadIdx.x;
    const int q = tid & 7, o = tid >> 3;
    const int g0 = (o & 7) * 8, c0 = (o >> 3) * 8;
    float acc[8][8];
    #pragma unroll
    for (int i = 0; i < 8; ++i)
        #pragma unroll
        for (int j = 0; j < 8; ++j) acc[i][j] = 0.f;
    float dacc[8] = {0, 0, 0, 0, 0, 0, 0, 0};
    for (int nt = 0; nt < 1024; nt += 32) {
        __syncthreads();
        {
            int rr = tid >> 3, p = tid & 7;
            size_t base = ((size_t)(b * NN + n0 + nt + rr)) * 512 + h * 64 + p * 8;
            uint4 uh = *(const uint4*)&g_swh[base];
            uint4 ul = *(const uint4*)&g_swl[base];
            const __nv_bfloat162* ph = (const __nv_bfloat162*)&uh;
            const __nv_bfloat162* pl = (const __nv_bfloat162*)&ul;
            #pragma unroll
            for (int t2 = 0; t2 < 4; ++t2) {
                float2 fh = __bfloat1622float2(ph[t2]);
                float2 fl = __bfloat1622float2(pl[t2]);
                sws[rr][p * 8 + t2 * 2] = fh.x + fl.x;
                sws[rr][p * 8 + t2 * 2 + 1] = fh.y + fl.y;
            }
            *(float4*)&fxs[rr][p * 4] =
                *(const float4*)&g_fx[((size_t)(b * NN + n0 + nt + rr)) * 256 + h * 32 + p * 4];
        }
        __syncthreads();
        #pragma unroll
        for (int i = 0; i < 4; ++i) {
            int nn = q + 8 * i;
            float sg[8], fc[8];
            *(float4*)sg = *(float4*)&sws[nn][g0];
            *(float4*)(sg + 4) = *(float4*)&sws[nn][g0 + 4];
            *(float4*)fc = *(float4*)&fxs[nn][c0];
            *(float4*)(fc + 4) = *(float4*)&fxs[nn][c0 + 4];
            if (c0 == 0)
                #pragma unroll
                for (int j = 0; j < 8; ++j) dacc[j] += sg[j];
            #pragma unroll
            for (int gi = 0; gi < 8; ++gi)
                #pragma unroll
                for (int ci = 0; ci < 8; ++ci) acc[gi][ci] += sg[gi] * fc[ci];
        }
    }
    #pragma unroll
    for (int d = 1; d < 8; d <<= 1)
        #pragma unroll
        for (int gi = 0; gi < 8; ++gi)
            #pragma unroll
            for (int ci = 0; ci < 8; ++ci)
                acc[gi][ci] += __shfl_xor_sync(0xffffffffu, acc[gi][ci], d);
    if (c0 == 0)
        #pragma unroll
        for (int d = 1; d < 8; d <<= 1)
            #pragma unroll
            for (int j = 0; j < 8; ++j) dacc[j] += __shfl_xor_sync(0xffffffffu, dacc[j], d);
    if (q == 0) {
        #pragma unroll
        for (int gi = 0; gi < 8; ++gi)
            #pragma unroll
            for (int ci = 0; ci < 8; ++ci)
                atomicAdd(&g_num[(bh * 64 + g0 + gi) * 32 + c0 + ci], acc[gi][ci]);
        if (c0 == 0)
            #pragma unroll
            for (int j = 0; j < 8; ++j) atomicAdd(&g_den[bh * 64 + g0 + j], dacc[j]);
    }
}

// ---------------- K3: slice_att -> qkv -> SDPA -> fold Wout -> g_Mb -------------
__global__ __launch_bounds__(256) void k3(const float* __restrict__ Wqkv,
                                          const float* __restrict__ Wout) {
    __shared__ float sa[64 * 32];
    __shared__ float qs[64 * 32], ks2[64 * 32], vs[64 * 32];
    __shared__ float wq[96 * 32];
    const int bh = blockIdx.x, b = bh >> 3, h = bh & 7;
    const int tid = threadIdx.x;
    for (int i = tid; i < 96 * 32; i += 256) wq[i] = Wqkv[i];
    #pragma unroll
    for (int c = 0; c < 8; ++c) {
        int idx = tid * 8 + c;
        sa[idx] = g_num[bh * 2048 + idx] / (g_den[bh * 64 + (idx >> 5)] + 1e-5f);
    }
    __syncthreads();
    for (int t = tid; t < 6144; t += 256) {
        int g = t & 63, j = t >> 6;
        float s2 = 0.f;
        #pragma unroll
        for (int c = 0; c < 32; ++c) s2 += sa[g * 32 + c] * wq[j * 32 + c];
        if (j < 32) qs[g * 32 + j] = s2;
        else if (j < 64) ks2[g * 32 + (j - 32)] = s2;
        else vs[g * 32 + (j - 64)] = s2;
    }
    __syncthreads();
    if (tid < 64) {
        int g = tid;
        float sc[64], m = -1e30f;
        #pragma unroll 8
        for (int kk = 0; kk < 64; ++kk) {
            float s2 = 0.f;
            #pragma unroll
            for (int c = 0; c < 32; ++c) s2 += qs[g * 32 + c] * ks2[kk * 32 + c];
            s2 *= 0.17677669529663687f;
            sc[kk] = s2;
            m = fmaxf(m, s2);
        }
        float ssum = 0.f;
        #pragma unroll
        for (int kk = 0; kk < 64; ++kk) { sc[kk] = __expf(sc[kk] - m); ssum += sc[kk]; }
        float inv = 1.0f / ssum;
        float att[32];
        #pragma unroll
        for (int c = 0; c < 32; ++c) att[c] = 0.f;
        #pragma unroll 8
        for (int kk = 0; kk < 64; ++kk) {
            float p = sc[kk] * inv;
            #pragma unroll
            for (int c = 0; c < 32; ++c) att[c] += p * vs[kk * 32 + c];
        }
        __syncwarp();
        #pragma unroll
        for (int c = 0; c < 32; ++c) sa[g * 32 + c] = att[c];
    }
    __syncthreads();
    int d2 = tid;
    for (int g = 0; g < 64; ++g) {
        float s2 = 0.f;
        #pragma unroll
        for (int c = 0; c < 32; ++c) s2 += sa[g * 32 + c] * Wout[d2 * 256 + h * 32 + c];
        __nv_bfloat16 h16 = __float2bfloat16(s2);
        __nv_bfloat16 l16 = __float2bfloat16(s2 - __bfloat162float(h16));
        size_t o0 = (size_t)b * 256 * 1536 + (size_t)d2 * 1536 + h * 64 + g;
        g_Mb[o0] = h16;
        g_Mb[o0 + 512] = l16;
        g_Mb[o0 + 1024] = h16;
    }
}

// ---------------- K4: out = sw @ M + bout (mma.sync, K'=1536) ----------------
__global__ __launch_bounds__(256) void k4(float* __restrict__ out,
                                          const float* __restrict__ bout) {
    extern __shared__ char sm[];
    uint32_t sb = s2u(sm);
    const int tid = threadIdx.x, lane = tid & 31, wid = tid >> 5;
    const int wm = wid & 3, wn = wid >> 2;
    const int y = blockIdx.x;                    // 0..1
    const int b = blockIdx.y >> 8, t0 = (blockIdx.y & 255) * 128;
    float* bias = (float*)(sm + 65536);
    if (tid < 128) bias[tid] = bout[y * 128 + tid];

    const __nv_bfloat16* swh = g_swh + (size_t)(b * NN + t0) * 512;
    const __nv_bfloat16* swl = g_swl + (size_t)(b * NN + t0) * 512;
    const __nv_bfloat16* Bsrc = g_Mb + (size_t)b * 256 * 1536 + (size_t)(y * 128) * 1536;

    float acc[2][8][4];
    #pragma unroll
    for (int i = 0; i < 2; ++i)
        #pragma unroll
        for (int j = 0; j < 8; ++j)
            #pragma unroll
            for (int k = 0; k < 4; ++k) acc[i][j][k] = 0.f;

    const int NCHK = 24;
    stage(sb, swh, 512);
    stage(sb + 32768, Bsrc, 1536);
    cpa_commit();
    #pragma unroll 1
    for (int c = 0; c < NCHK; ++c) {
        uint32_t ab = sb + (c & 1) * 16384, bb = sb + 32768 + (c & 1) * 16384;
        if (c + 1 < NCHK) {
            int kc = (c + 1) * 64;
            const __nv_bfloat16* as = (kc < 1024) ? swh + (kc & 511) : swl + (kc - 1024);
            stage(sb + ((c + 1) & 1) * 16384, as, 512);
            stage(sb + 32768 + ((c + 1) & 1) * 16384, Bsrc + kc, 1536);
            cpa_commit();
            cpa_wait<1>();
        } else {
            cpa_wait<0>();
        }
        __syncthreads();
        compute_chunk(ab, bb, wm, wn, lane, acc);
        __syncthreads();
    }

    const int q = lane & 3, qr = lane >> 2;
    const int cbl = wn * 64;
    #pragma unroll
    for (int mf = 0; mf < 2; ++mf)
        #pragma unroll
        for (int half = 0; half < 2; ++half) {
            int rl = wm * 32 + mf * 16 + qr + half * 8;
            float* op = out + (size_t)(b * NN + t0 + rl) * 256 + y * 128 + cbl;
            #pragma unroll
            for (int nf = 0; nf < 8; ++nf) {
                float v0 = acc[mf][nf][half * 2 + 0] + bias[cbl + nf * 8 + q * 2 + 0];
                float v1 = acc[mf][nf][half * 2 + 1] + bias[cbl + nf * 8 + q * 2 + 1];
                *(float2*)(op + nf * 8 + q * 2) = make_float2(v0, v1);
            }
        }
}

extern "C" void kernel_launch(void* const* d_in, const int* in_sizes, int n_in,
                              void* d_out, int out_size) {
    const float* x = (const float*)d_in[0];
    const float* Wx = (const float*)d_in[1];
    const float* bx = (const float*)d_in[2];
    const float* Wfx = (const float*)d_in[3];
    const float* bfx = (const float*)d_in[4];
    const float* Wsl = (const float*)d_in[5];
    const float* bsl = (const float*)d_in[6];
    const float* temp = (const float*)d_in[7];
    const float* Wqkv = (const float*)d_in[8];
    const float* Wout = (const float*)d_in[9];
    const float* bout = (const float*)d_in[10];
    float* out = (float*)d_out;

    const int SMEM = 65536 + 1024;
    cudaFuncSetAttribute(k1, cudaFuncAttributeMaxDynamicSharedMemorySize, SMEM);
    cudaFuncSetAttribute(k4, cudaFuncAttributeMaxDynamicSharedMemorySize, SMEM);

    k0<<<768, 256>>>(Wx, bx, Wfx, bfx, Wsl, bsl, temp);
    kprep<<<16384, 256>>>(x);
    kzero<<<(2 * 8 * 64 * 32 + 2 * 8 * 64 + 255) / 256, 256>>>();
    k1<<<dim3(6, 512), 256, SMEM>>>();
    k2<<<dim3(32, 16), 256>>>();
    k3<<<16, 256>>>(Wqkv, Wout);
    k4<<<dim3(2, 512), 256, SMEM>>>(out, bout);
}